// round 9
// baseline (speedup 1.0000x reference)
#include <cuda_runtime.h>
#include <cstdint>

// Problem constants (from reference)
#define DD   41
#define CCH  64
#define CHT  105          // DD + CCH
#define FH_  32
#define FW_  88
#define B_   4
#define NX0_ 200
#define NZ_  200
#define COLH (CHT * FH_)  // 3360 floats per (b,w) column in xT
#define OUTN  (B_ * CCH * NZ_ * NX0_)   // 10,240,000 floats
#define FPAD 36           // sf pitch: 16B-aligned rows, conflict-free LDS.128

// Static scratch: x transposed to [b][w][ch][h] (4.73 MB)
__device__ float g_xT[(size_t)B_ * FW_ * COLH];

// ---------------------------------------------------------------------------
// Kernel 1: fused (a) zero-fill of out and (b) transpose
// x[b][ch*32+h][w] -> xT[b][w][ch*32+h].  grid (105, 3, 4) x 256 thr.
// (~50 MB traffic: at the HBM write roofline already)
// ---------------------------------------------------------------------------
__global__ __launch_bounds__(256) void lss_prep(const float* __restrict__ x,
                                                float* __restrict__ out) {
    __shared__ float tile[32][33];
    const int tx  = threadIdx.x & 31;
    const int ty  = threadIdx.x >> 5;
    const int tid = threadIdx.x;

    // (a) zero my slice of out (float4, grid-strided)
    {
        const int nblk = gridDim.x * gridDim.y * gridDim.z;
        const int lin  = (blockIdx.z * gridDim.y + blockIdx.y) * gridDim.x
                       + blockIdx.x;
        float4* o4 = (float4*)out;
        const int n4 = OUTN / 4;
        const float4 z4 = make_float4(0.f, 0.f, 0.f, 0.f);
        for (int i = lin * 256 + tid; i < n4; i += nblk * 256) o4[i] = z4;
    }

    // (b) 32x32 tile transpose
    const int b  = blockIdx.z;
    const int r0 = blockIdx.x * 32;
    const int c0 = blockIdx.y * 32;

    const float* xb = x + (size_t)b * COLH * FW_;
#pragma unroll
    for (int i = ty; i < 32; i += 8) {
        int r = r0 + i, c = c0 + tx;
        if (c < FW_) tile[i][tx] = xb[(size_t)r * FW_ + c];
    }
    __syncthreads();
    float* xt = g_xT + (size_t)b * FW_ * COLH;
#pragma unroll
    for (int i = ty; i < 32; i += 8) {
        int w = c0 + i, r = r0 + tx;
        if (w < FW_) xt[(size_t)w * COLH + r] = tile[tx][i];
    }
}

// 3x3 inverse via adjugate, correctly-rounded divisions. Bit-sensitive; keep.
__device__ __forceinline__ void inv3(const float* m, float* o) {
    float a = m[0], b = m[1], c = m[2];
    float d = m[3], e = m[4], f = m[5];
    float g = m[6], h = m[7], i = m[8];
    float c00 = e * i - f * h;
    float c01 = f * g - d * i;
    float c02 = d * h - e * g;
    float det = a * c00 + b * c01 + c * c02;
    o[0] = __fdiv_rn(c00, det);
    o[1] = __fdiv_rn(c * h - b * i, det);
    o[2] = __fdiv_rn(b * f - c * e, det);
    o[3] = __fdiv_rn(c01, det);
    o[4] = __fdiv_rn(a * i - c * g, det);
    o[5] = __fdiv_rn(c * d - a * f, det);
    o[6] = __fdiv_rn(c02, det);
    o[7] = __fdiv_rn(b * g - a * h, det);
    o[8] = __fdiv_rn(a * e - b * d, det);
}

// ---------------------------------------------------------------------------
// Kernel 2: main. One block per (w, b, c-half). 256 threads = 8 warps.
//  P1a: logits -> wts[41][32] smem (contiguous float4)        [duplicated]
//  P1b: 32-channel feature half -> sf[32][36] (ONE float4/thread, coalesced)
//  P2 : single-pass group softmax (per-warp-group max/sum + scale table,
//       only 2 barriers)                                      [duplicated]
//  P3 : geometry per (d,h); uniformity ballot; normalize via hoisted scale
//  P4 : warp wg owns d = wg+8k for 32 channels (lane = c-local);
//       f regs via conflict-free LDS.128; wts via broadcast LDS.128;
//       ONE REDG per (d, channel) chip-wide (unchanged total).
// ---------------------------------------------------------------------------
__global__ __launch_bounds__(256) void lss_main(
    const float* __restrict__ intrins,
    const float* __restrict__ rots,
    const float* __restrict__ trans,
    float* __restrict__ out)
{
    __shared__ float wts[DD][FH_];      // logits -> exp(v-m_g) -> weights
    __shared__ float sf[32][FPAD];      // [c-local][h] feature half
    __shared__ float pm[8][FH_];        // per-group max
    __shared__ float ps[8][FH_];        // per-group sum
    __shared__ float scale[8][FH_];     // exp(m_g - m) / s
    __shared__ int   binsp[DD];
    __shared__ int   flags[DD];         // 0 = no kept, 1 = uniform, 2 = mixed
    __shared__ int   binh[DD][FH_];
    __shared__ float iR[9], iK[9], tv[3];

    const int w      = blockIdx.x;
    const int b      = blockIdx.y;
    const int c0base = blockIdx.z << 5;        // 0 or 32
    const int tid    = threadIdx.x;
    const int lane   = tid & 31;
    const int wg     = tid >> 5;               // 0..7

    const float* xt = g_xT + ((size_t)b * FW_ + w) * COLH;

    // P1a: logits 41x32 (contiguous) -> smem via float4
    {
        const float4* src = (const float4*)xt;
        float4* dst = (float4*)&wts[0][0];
        for (int i = tid; i < (DD * FH_) / 4; i += 256) dst[i] = src[i];
    }
    // P1b: feature half 32x32 -> sf: exactly one float4 per thread
    {
        const float4* src = (const float4*)(xt + (size_t)(DD + c0base) * FH_);
        float4 v = src[tid];
        int cc = tid >> 3, h4 = (tid & 7) << 2;
        float* p = &sf[cc][h4];
        p[0] = v.x; p[1] = v.y; p[2] = v.z; p[3] = v.w;
    }
    if (tid == 0) {
        float mr[9], mk[9];
#pragma unroll
        for (int k = 0; k < 9; k++) { mr[k] = rots[b * 9 + k]; mk[k] = intrins[b * 9 + k]; }
        inv3(mr, iR);
        inv3(mk, iK);
        tv[0] = trans[b * 3 + 0]; tv[1] = trans[b * 3 + 1]; tv[2] = trans[b * 3 + 2];
    }
    __syncthreads();

    // P2: single-pass group softmax. Thread (wg, lane): d = wg + 8k.
    // Stores e = exp(v - m_g) in wts; group scale fixes up later.
    {
        float m_t = -3.402823466e38f;
        for (int d = wg; d < DD; d += 8) m_t = fmaxf(m_t, wts[d][lane]);
        float s_t = 0.f;
        for (int d = wg; d < DD; d += 8) {
            float e = __expf(wts[d][lane] - m_t);
            wts[d][lane] = e;
            s_t += e;
        }
        pm[wg][lane] = m_t;
        ps[wg][lane] = s_t;
    }
    __syncthreads();
    if (tid < 32) {
        float m = pm[0][lane];
#pragma unroll
        for (int g = 1; g < 8; g++) m = fmaxf(m, pm[g][lane]);
        float s = 0.f;
#pragma unroll
        for (int g = 0; g < 8; g++) s += ps[g][lane] * __expf(pm[g][lane] - m);
        float rinv = __frcp_rn(s);
#pragma unroll
        for (int g = 0; g < 8; g++) scale[g][lane] = __expf(pm[g][lane] - m) * rinv;
    }
    __syncthreads();

    // P3: geometry. warp wg handles d = wg, wg+8, ...; lane = h.
    {
        const float xs = (float)w    * (703.0f / 87.0f);
        const float ys = (float)lane * (255.0f / 31.0f);
        const float r00 = iR[0], r01 = iR[1], r02 = iR[2];
        const float r10 = iR[3], r11 = iR[4], r12 = iR[5];
        const float r20 = iR[6], r21 = iR[7], r22 = iR[8];
        const float k00 = iK[0], k01 = iK[1], k02 = iK[2];
        const float k10 = iK[3], k11 = iK[4], k12 = iK[5];
        const float k20 = iK[6], k21 = iK[7], k22 = iK[8];
        const float t0 = tv[0], t1 = tv[1], t2 = tv[2];
        const float p0 = xs - t0, p1 = ys - t1;
        const float sc = scale[wg][lane];    // group of d = wg for all its d

        for (int d = wg; d < DD; d += 8) {
            float p2 = (4.0f + (float)d) - t2;
            float q0 = __fmaf_rn(r00, p0, __fmaf_rn(r01, p1, r02 * p2));
            float q1 = __fmaf_rn(r10, p0, __fmaf_rn(r11, p1, r12 * p2));
            float q2 = __fmaf_rn(r20, p0, __fmaf_rn(r21, p1, r22 * p2));
            float s0 = q0 * q2, s1 = q1 * q2, s2 = q2;
            float g0 = __fmaf_rn(k00, s0, __fmaf_rn(k01, s1, k02 * s2));
            float g1 = __fmaf_rn(k10, s0, __fmaf_rn(k11, s1, k12 * s2));
            float g2 = __fmaf_rn(k20, s0, __fmaf_rn(k21, s1, k22 * s2));
            // truncation toward zero matches astype(int32)
            int c0i = (int)((g0 + 50.0f) / 0.5f);
            int c1i = (int)((g1 + 10.0f) / 20.0f);
            int c2i = (int)(g2 / 0.25f);
            bool kept = (c0i >= 0) & (c0i < NX0_) & (c1i >= 0) & (c1i < 1) &
                        (c2i >= 0) & (c2i < NZ_);
            int sp = c2i * NX0_ + c0i;
            binh[d][lane] = sp;
            float wv = kept ? wts[d][lane] * sc : 0.0f;
            wts[d][lane] = wv;

            unsigned km = __ballot_sync(0xffffffffu, kept);
            int fl = 0;
            if (km) {
                int src = __ffs(km) - 1;
                int lsp = __shfl_sync(0xffffffffu, sp, src);
                bool ok = (!kept) || (sp == lsp);
                fl = __all_sync(0xffffffffu, ok) ? 1 : 2;
                if (lane == 0) binsp[d] = lsp;
            }
            if (lane == 0) flags[d] = fl;
        }
    }
    __syncthreads();

    // P4: matvec + scatter. warp wg owns d = wg+8k; lane = c-local.
    // f regs via conflict-free LDS.128 from sf (pitch 36: per-phase banks
    // 4i mod 32 distinct); wts rows via broadcast LDS.128.
    {
        float f[FH_];
        {
            const float4* sfc = (const float4*)&sf[lane][0];
#pragma unroll
            for (int k = 0; k < 8; k++) {
                float4 v = sfc[k];
                f[4 * k + 0] = v.x; f[4 * k + 1] = v.y;
                f[4 * k + 2] = v.z; f[4 * k + 3] = v.w;
            }
        }

        float* ob = out + ((size_t)b * CCH + c0base + lane) * (NZ_ * NX0_);
        for (int d = wg; d < DD; d += 8) {
            int fl = flags[d];
            if (fl == 0) continue;
            if (fl == 1) {
                const float4* wr = (const float4*)&wts[d][0];
                float a0 = 0.f, a1 = 0.f, a2 = 0.f, a3 = 0.f;
#pragma unroll
                for (int k = 0; k < 8; k++) {
                    float4 wv4 = wr[k];              // broadcast LDS.128
                    a0 = __fmaf_rn(wv4.x, f[4 * k + 0], a0);
                    a1 = __fmaf_rn(wv4.y, f[4 * k + 1], a1);
                    a2 = __fmaf_rn(wv4.z, f[4 * k + 2], a2);
                    a3 = __fmaf_rn(wv4.w, f[4 * k + 3], a3);
                }
                atomicAdd(ob + binsp[d], (a0 + a1) + (a2 + a3));
            } else {
                // generic fallback: per-h scatter
#pragma unroll
                for (int h = 0; h < FH_; h++) {
                    float wv = wts[d][h];
                    if (wv != 0.f) atomicAdd(ob + binh[d][h], wv * f[h]);
                }
            }
        }
    }
}

// ---------------------------------------------------------------------------
extern "C" void kernel_launch(void* const* d_in, const int* in_sizes, int n_in,
                              void* d_out, int out_size) {
    const float* x       = (const float*)d_in[0];
    const float* intrins = (const float*)d_in[1];
    const float* rots    = (const float*)d_in[2];
    const float* trans   = (const float*)d_in[3];
    float* out = (float*)d_out;

    // fused zero-fill + transpose
    dim3 pgrid(COLH / 32, (FW_ + 31) / 32, B_);   // (105, 3, 4)
    lss_prep<<<pgrid, 256>>>(x, out);

    // main: c-split doubles the grid (704 blocks) for latency hiding
    dim3 mgrid(FW_, B_, 2);
    lss_main<<<mgrid, 256>>>(intrins, rots, trans, out);
}

// round 10
// speedup vs baseline: 1.0935x; 1.0935x over previous
#include <cuda_runtime.h>
#include <cstdint>

// Problem constants (from reference)
#define DD   41
#define CCH  64
#define CHT  105          // DD + CCH
#define FH_  32
#define FW_  88
#define B_   4
#define NX0_ 200
#define NZ_  200
#define COLH (CHT * FH_)  // 3360 floats per (b,w) column
#define OUTN  (B_ * CCH * NZ_ * NX0_)   // 10,240,000 floats
#define HH   16           // h per block (h-split)
#define SPAD 20           // sf pitch (conflict-free LDS.128, 16B-aligned)

// Static scratch: x rearranged to [b][w][hhalf][ch][16] (4.73 MB)
__device__ float g_xT[(size_t)B_ * FW_ * 2 * CHT * HH];

// ---------------------------------------------------------------------------
// Kernel 1: fused (a) zero-fill of out and (b) rearrange
// x[b][ch*32+h][w] -> xT[b][w][h>>4][ch][h&15].  grid (105, 3, 4) x 256 thr.
// ---------------------------------------------------------------------------
__global__ __launch_bounds__(256) void lss_prep(const float* __restrict__ x,
                                                float* __restrict__ out) {
    __shared__ float tile[32][33];
    const int tx  = threadIdx.x & 31;
    const int ty  = threadIdx.x >> 5;
    const int tid = threadIdx.x;

    // (a) zero my slice of out (float4, grid-strided)
    {
        const int nblk = gridDim.x * gridDim.y * gridDim.z;
        const int lin  = (blockIdx.z * gridDim.y + blockIdx.y) * gridDim.x
                       + blockIdx.x;
        float4* o4 = (float4*)out;
        const int n4 = OUTN / 4;
        const float4 z4 = make_float4(0.f, 0.f, 0.f, 0.f);
        for (int i = lin * 256 + tid; i < n4; i += nblk * 256) o4[i] = z4;
    }

    // (b) 32x32 tile transpose + h-split write layout
    const int b  = blockIdx.z;
    const int r0 = blockIdx.x * 32;   // r = ch*32 + h; r0 multiple of 32 => ch fixed
    const int c0 = blockIdx.y * 32;   // w

    const float* xb = x + (size_t)b * COLH * FW_;
#pragma unroll
    for (int i = ty; i < 32; i += 8) {
        int r = r0 + i, c = c0 + tx;
        if (c < FW_) tile[i][tx] = xb[(size_t)r * FW_ + c];
    }
    __syncthreads();
    const int ch = r0 >> 5;           // whole tile is one channel row
    float* xtb = g_xT + (size_t)b * FW_ * 2 * CHT * HH;
#pragma unroll
    for (int i = ty; i < 32; i += 8) {
        int w = c0 + i;
        int h = tx;                   // r = r0 + tx -> h = tx
        if (w < FW_) {
            size_t addr = (((size_t)w * 2 + (h >> 4)) * CHT + ch) * HH + (h & 15);
            xtb[addr] = tile[tx][i];
        }
    }
}

// 3x3 inverse via adjugate, correctly-rounded divisions. Bit-sensitive; keep.
__device__ __forceinline__ void inv3(const float* m, float* o) {
    float a = m[0], b = m[1], c = m[2];
    float d = m[3], e = m[4], f = m[5];
    float g = m[6], h = m[7], i = m[8];
    float c00 = e * i - f * h;
    float c01 = f * g - d * i;
    float c02 = d * h - e * g;
    float det = a * c00 + b * c01 + c * c02;
    o[0] = __fdiv_rn(c00, det);
    o[1] = __fdiv_rn(c * h - b * i, det);
    o[2] = __fdiv_rn(b * f - c * e, det);
    o[3] = __fdiv_rn(c01, det);
    o[4] = __fdiv_rn(a * i - c * g, det);
    o[5] = __fdiv_rn(c * d - a * f, det);
    o[6] = __fdiv_rn(c02, det);
    o[7] = __fdiv_rn(b * g - a * h, det);
    o[8] = __fdiv_rn(a * e - b * d, det);
}

// ---------------------------------------------------------------------------
// Kernel 2: main. One block per (w, b, hhalf). 256 threads = 8 warps.
// ZERO front-end duplication: each block loads/computes only its 16 h's.
//  P1 : contiguous 6.72KB -> wts[41][16] + sf[64][20]
//  P2 : single-pass group softmax (group g = tid>>4 covers d = g+16k)
//  P3 : geometry, half-warp (16-lane) uniformity ballots
//  P4 : warp=(dg,chalf), lane=c; f[16] regs (conflict-free LDS.128);
//       broadcast LDS.128 weights; ONE REDG per (d, c).
// ---------------------------------------------------------------------------
__global__ __launch_bounds__(256) void lss_main(
    const float* __restrict__ intrins,
    const float* __restrict__ rots,
    const float* __restrict__ trans,
    float* __restrict__ out)
{
    __shared__ float wts[DD][HH];       // logits -> exp(v-m_g) -> weights
    __shared__ float sf[CCH][SPAD];     // [c][hh] feature stage
    __shared__ float pm[16][17];        // per-group max
    __shared__ float ps[16][17];        // per-group sum
    __shared__ float scale[16][17];     // exp(m_g - m)/s
    __shared__ int   binsp[DD];
    __shared__ int   flags[DD];         // 0 = no kept, 1 = uniform, 2 = mixed
    __shared__ int   binh[DD][HH];
    __shared__ float iR[9], iK[9], tv[3];

    const int w    = blockIdx.x;
    const int b    = blockIdx.y;
    const int half = blockIdx.z;               // 0 or 1
    const int tid  = threadIdx.x;
    const int lane = tid & 31;
    const int wg   = tid >> 5;                 // 0..7
    const int g    = tid >> 4;                 // 0..15 (softmax/geometry group)
    const int hh   = tid & 15;                 // h within half

    const float* xt = g_xT + (((size_t)b * FW_ + w) * 2 + half) * (CHT * HH);

    // P1: one contiguous 6.72KB chunk -> smem (420 float4, <2 per thread)
    {
        const float4* src = (const float4*)xt;
        for (int i = tid; i < (CHT * HH) / 4; i += 256) {
            float4 v = src[i];
            int ch = i >> 2, h4 = (i & 3) << 2;
            float* p = (ch < DD) ? &wts[ch][h4] : &sf[ch - DD][h4];
            p[0] = v.x; p[1] = v.y; p[2] = v.z; p[3] = v.w;
        }
    }
    if (tid == 0) {
        float mr[9], mk[9];
#pragma unroll
        for (int k = 0; k < 9; k++) { mr[k] = rots[b * 9 + k]; mk[k] = intrins[b * 9 + k]; }
        inv3(mr, iR);
        inv3(mk, iK);
        tv[0] = trans[b * 3 + 0]; tv[1] = trans[b * 3 + 1]; tv[2] = trans[b * 3 + 2];
    }
    __syncthreads();

    // P2: group softmax. Thread (g, hh): d = g, g+16, g+32.
    {
        float m_t = -3.402823466e38f;
        for (int d = g; d < DD; d += 16) m_t = fmaxf(m_t, wts[d][hh]);
        float s_t = 0.f;
        for (int d = g; d < DD; d += 16) {
            float e = __expf(wts[d][hh] - m_t);
            wts[d][hh] = e;
            s_t += e;
        }
        pm[g][hh] = m_t;
        ps[g][hh] = s_t;
    }
    __syncthreads();
    if (tid < 16) {
        const int h = tid;
        float m = pm[0][h];
#pragma unroll
        for (int gg = 1; gg < 16; gg++) m = fmaxf(m, pm[gg][h]);
        float s = 0.f;
#pragma unroll
        for (int gg = 0; gg < 16; gg++) s += ps[gg][h] * __expf(pm[gg][h] - m);
        float rinv = __frcp_rn(s);
#pragma unroll
        for (int gg = 0; gg < 16; gg++) scale[gg][h] = __expf(pm[gg][h] - m) * rinv;
    }
    __syncthreads();

    // P3: geometry. Group g handles d = g + 16k; 16 lanes = h within half.
    {
        const int hglob = half * HH + hh;
        const float xs = (float)w     * (703.0f / 87.0f);
        const float ys = (float)hglob * (255.0f / 31.0f);
        const float r00 = iR[0], r01 = iR[1], r02 = iR[2];
        const float r10 = iR[3], r11 = iR[4], r12 = iR[5];
        const float r20 = iR[6], r21 = iR[7], r22 = iR[8];
        const float k00 = iK[0], k01 = iK[1], k02 = iK[2];
        const float k10 = iK[3], k11 = iK[4], k12 = iK[5];
        const float k20 = iK[6], k21 = iK[7], k22 = iK[8];
        const float t0 = tv[0], t1 = tv[1], t2 = tv[2];
        const float p0 = xs - t0, p1 = ys - t1;
        const float sc = scale[g][hh];
        const unsigned hm = 0xFFFFu << ((g & 1) * 16);   // my half-warp mask

        for (int d = g; d < DD; d += 16) {
            float p2 = (4.0f + (float)d) - t2;
            float q0 = __fmaf_rn(r00, p0, __fmaf_rn(r01, p1, r02 * p2));
            float q1 = __fmaf_rn(r10, p0, __fmaf_rn(r11, p1, r12 * p2));
            float q2 = __fmaf_rn(r20, p0, __fmaf_rn(r21, p1, r22 * p2));
            float s0 = q0 * q2, s1 = q1 * q2, s2 = q2;
            float g0 = __fmaf_rn(k00, s0, __fmaf_rn(k01, s1, k02 * s2));
            float g1 = __fmaf_rn(k10, s0, __fmaf_rn(k11, s1, k12 * s2));
            float g2 = __fmaf_rn(k20, s0, __fmaf_rn(k21, s1, k22 * s2));
            // truncation toward zero matches astype(int32)
            int c0i = (int)((g0 + 50.0f) / 0.5f);
            int c1i = (int)((g1 + 10.0f) / 20.0f);
            int c2i = (int)(g2 / 0.25f);
            bool kept = (c0i >= 0) & (c0i < NX0_) & (c1i >= 0) & (c1i < 1) &
                        (c2i >= 0) & (c2i < NZ_);
            int sp = c2i * NX0_ + c0i;
            binh[d][hh] = sp;
            wts[d][hh] = kept ? wts[d][hh] * sc : 0.0f;

            unsigned km = __ballot_sync(hm, kept);
            int fl = 0;
            if (km) {
                int src = __ffs(km) - 1;                 // absolute lane in warp
                int lsp = __shfl_sync(hm, sp, src);
                bool ok = (!kept) || (sp == lsp);
                fl = __all_sync(hm, ok) ? 1 : 2;
                if (hh == 0) binsp[d] = lsp;
            }
            if (hh == 0) flags[d] = fl;
        }
    }
    __syncthreads();

    // P4: matvec + scatter. warp wg: chalf = wg&1, dg = wg>>1 (0..3);
    // lane owns channel c = chalf*32 + lane.
    {
        const int c = ((wg & 1) << 5) + lane;
        float f[HH];
        {
            const float4* sfc = (const float4*)&sf[c][0];
#pragma unroll
            for (int k = 0; k < 4; k++) {
                float4 v = sfc[k];
                f[4 * k + 0] = v.x; f[4 * k + 1] = v.y;
                f[4 * k + 2] = v.z; f[4 * k + 3] = v.w;
            }
        }

        float* ob = out + ((size_t)b * CCH + c) * (NZ_ * NX0_);
        for (int d = (wg >> 1); d < DD; d += 4) {
            int fl = flags[d];
            if (fl == 0) continue;
            if (fl == 1) {
                const float4* wr = (const float4*)&wts[d][0];
                float a0 = 0.f, a1 = 0.f, a2 = 0.f, a3 = 0.f;
#pragma unroll
                for (int k = 0; k < 4; k++) {
                    float4 wv4 = wr[k];                  // broadcast LDS.128
                    a0 = __fmaf_rn(wv4.x, f[4 * k + 0], a0);
                    a1 = __fmaf_rn(wv4.y, f[4 * k + 1], a1);
                    a2 = __fmaf_rn(wv4.z, f[4 * k + 2], a2);
                    a3 = __fmaf_rn(wv4.w, f[4 * k + 3], a3);
                }
                atomicAdd(ob + binsp[d], (a0 + a1) + (a2 + a3));
            } else {
                // generic fallback: per-h scatter over this half's 16 h
#pragma unroll
                for (int h = 0; h < HH; h++) {
                    float wv = wts[d][h];
                    if (wv != 0.f) atomicAdd(ob + binh[d][h], wv * f[h]);
                }
            }
        }
    }
}

// ---------------------------------------------------------------------------
extern "C" void kernel_launch(void* const* d_in, const int* in_sizes, int n_in,
                              void* d_out, int out_size) {
    const float* x       = (const float*)d_in[0];
    const float* intrins = (const float*)d_in[1];
    const float* rots    = (const float*)d_in[2];
    const float* trans   = (const float*)d_in[3];
    float* out = (float*)d_out;

    // fused zero-fill + rearrange
    dim3 pgrid(COLH / 32, (FW_ + 31) / 32, B_);   // (105, 3, 4)
    lss_prep<<<pgrid, 256>>>(x, out);

    // main: h-split, zero duplication (704 blocks)
    dim3 mgrid(FW_, B_, 2);
    lss_main<<<mgrid, 256>>>(intrins, rots, trans, out);
}